// round 11
// baseline (speedup 1.0000x reference)
#include <cuda_runtime.h>
#include <cuda_bf16.h>
#include <cstdint>
#include <math.h>

// Shapes
#define BATCH 8
#define CDIM  1024      // channels == tokens
#define SPAT  1024      // 32*32 spatial
#define NH    16
#define HD    64
#define CONVK 9216      // 1024*9

// ---------------- scratch (device globals) ---------------------------------
__device__ __nv_bfloat16 g_whi[(size_t)3 * CDIM * CONVK];   // [conv][o][r*1024+i]
__device__ __nv_bfloat16 g_wlo[(size_t)3 * CDIM * CONVK];
__device__ __nv_bfloat16 g_ihi[(size_t)24 * SPAT * CDIM];   // [conv*8+b][pix][i]
__device__ __nv_bfloat16 g_ilo[(size_t)24 * SPAT * CDIM];
__device__ __nv_bfloat16 g_chi[(size_t)24 * CDIM * SPAT];   // conv out hi [z][o][pix]
__device__ __nv_bfloat16 g_clo[(size_t)24 * CDIM * SPAT];
__device__ __nv_bfloat16 g_vthi[(size_t)BATCH * SPAT * CDIM]; // V^T [b][d][s]
__device__ __nv_bfloat16 g_vtlo[(size_t)BATCH * SPAT * CDIM];
__device__ __nv_bfloat16 g_wohi[(size_t)CDIM * CDIM];
__device__ __nv_bfloat16 g_wolo[(size_t)CDIM * CDIM];
__device__ __nv_bfloat16 g_aohi[(size_t)BATCH * CDIM * SPAT];
__device__ __nv_bfloat16 g_aolo[(size_t)BATCH * CDIM * SPAT];

// ---------------- PTX helpers (sm_80-baseline only) ------------------------
__device__ __forceinline__ uint32_t smem_u32(const void* p) {
    uint32_t a;
    asm("{ .reg .u64 t; cvta.to.shared.u64 t, %1; cvt.u32.u64 %0, t; }" : "=r"(a) : "l"(p));
    return a;
}
__device__ __forceinline__ void cp_async16(uint32_t dst, const void* src, int src_bytes) {
    asm volatile("cp.async.cg.shared.global [%0], [%1], 16, %2;"
                 :: "r"(dst), "l"(src), "r"(src_bytes) : "memory");
}
#define CP_COMMIT() asm volatile("cp.async.commit_group;" ::: "memory")
#define CP_WAIT(n)  asm volatile("cp.async.wait_group %0;" :: "n"(n) : "memory")

#define LDSM_X4(r, a) \
    asm volatile("ldmatrix.sync.aligned.m8n8.x4.shared.b16 {%0,%1,%2,%3}, [%4];" \
                 : "=r"((r)[0]), "=r"((r)[1]), "=r"((r)[2]), "=r"((r)[3]) : "r"(a))

__device__ __forceinline__ void mma16816(float* c, const uint32_t* a, uint32_t b0, uint32_t b1) {
    asm volatile("mma.sync.aligned.m16n8k16.row.col.f32.bf16.bf16.f32 "
                 "{%0,%1,%2,%3},{%4,%5,%6,%7},{%8,%9},{%0,%1,%2,%3};"
                 : "+f"(c[0]), "+f"(c[1]), "+f"(c[2]), "+f"(c[3])
                 : "r"(a[0]), "r"(a[1]), "r"(a[2]), "r"(a[3]), "r"(b0), "r"(b1));
}

__device__ __forceinline__ void split_store2(__nv_bfloat16* hi, __nv_bfloat16* lo,
                                             size_t idx, float a, float b) {
    __nv_bfloat16 ha = __float2bfloat16(a), hb = __float2bfloat16(b);
    __nv_bfloat162 hv; hv.x = ha; hv.y = hb;
    *(__nv_bfloat162*)(hi + idx) = hv;
    __nv_bfloat162 lv;
    lv.x = __float2bfloat16(a - __bfloat162float(ha));
    lv.y = __float2bfloat16(b - __bfloat162float(hb));
    *(__nv_bfloat162*)(lo + idx) = lv;
}

// ---------------- precompute: weight split to [o][r*1024+i] ----------------
__global__ void split_w(const float* __restrict__ Wq, const float* __restrict__ Wk,
                        const float* __restrict__ Wv,
                        __nv_bfloat16* __restrict__ hi, __nv_bfloat16* __restrict__ lo) {
    const int o = blockIdx.x, conv = blockIdx.y;
    const float* W = (conv == 0 ? Wq : (conv == 1 ? Wk : Wv)) + (size_t)o * CONVK;
    size_t ob = ((size_t)conv * CDIM + o) * CONVK;
    for (int kk = threadIdx.x; kk < CONVK; kk += 256) {
        int r = kk >> 10, i = kk & 1023;
        float w = W[i * 9 + r];
        __nv_bfloat16 h = __float2bfloat16(w);
        hi[ob + kk] = h;
        lo[ob + kk] = __float2bfloat16(w - __bfloat162float(h));
    }
}

__global__ void split_wo(const float* __restrict__ Wo,
                         __nv_bfloat16* __restrict__ hi, __nv_bfloat16* __restrict__ lo) {
    int idx = blockIdx.x * 256 + threadIdx.x;
    float w = Wo[idx];
    __nv_bfloat16 h = __float2bfloat16(w);
    hi[idx] = h;
    lo[idx] = __float2bfloat16(w - __bfloat162float(h));
}

// ---------------- precompute: transpose + split inputs ---------------------
__global__ void transpose_split_in(const float* __restrict__ q, const float* __restrict__ k,
                                   const float* __restrict__ v,
                                   __nv_bfloat16* __restrict__ hi, __nv_bfloat16* __restrict__ lo) {
    __shared__ float t[32][33];
    const int z = blockIdx.z, conv = z >> 3, b = z & 7;
    const float* src = (conv == 0 ? q : (conv == 1 ? k : v)) + (size_t)b * CDIM * SPAT;
    const int i0 = blockIdx.y * 32, p0 = blockIdx.x * 32;
    const int tx = threadIdx.x, ty = threadIdx.y;
    #pragma unroll
    for (int r = ty; r < 32; r += 8) t[r][tx] = src[(size_t)(i0 + r) * SPAT + p0 + tx];
    __syncthreads();
    size_t base = (size_t)z * SPAT * CDIM;
    #pragma unroll
    for (int r = ty; r < 32; r += 8) {
        float w = t[tx][r];
        __nv_bfloat16 h = __float2bfloat16(w);
        size_t idx = base + (size_t)(p0 + r) * CDIM + i0 + tx;
        hi[idx] = h;
        lo[idx] = __float2bfloat16(w - __bfloat162float(h));
    }
}

// ---------------- bf16 transpose (V -> V^T) --------------------------------
__global__ void tr_bf16(const __nv_bfloat16* __restrict__ in, __nv_bfloat16* __restrict__ out) {
    __shared__ __nv_bfloat16 t[32][33];
    const int b = blockIdx.z, s0 = blockIdx.y * 32, d0 = blockIdx.x * 32;
    const __nv_bfloat16* ip = in + (size_t)b * CDIM * SPAT;
    __nv_bfloat16* op = out + (size_t)b * CDIM * SPAT;
    const int tx = threadIdx.x, ty = threadIdx.y;
    #pragma unroll
    for (int r = ty; r < 32; r += 8) t[r][tx] = ip[(size_t)(s0 + r) * SPAT + d0 + tx];
    __syncthreads();
    #pragma unroll
    for (int r = ty; r < 32; r += 8) op[(size_t)(d0 + r) * CDIM + s0 + tx] = t[tx][r];
}

// ---------------- conv via warp MMA: 128x128, BK=32, 2 stages, phase loop --
// Stage (32KB): rows 0-127 = A (hi chunks 0-3, lo chunks 4-7, c^(row&7) swizzle)
//               +16384 = B (same packing). Stage base constant per unrolled copy.
// Loop = 9 phases (conv tap r fixed) x 32 K-chunks; gather bounds hoisted per phase.
#define CV_STAGE 32768
#define CV_NIT   288    // 9216/32

__global__ __launch_bounds__(256, 2)
void conv_mma(const __nv_bfloat16* __restrict__ whi, const __nv_bfloat16* __restrict__ wlo,
              const __nv_bfloat16* __restrict__ ihi, const __nv_bfloat16* __restrict__ ilo,
              const float* __restrict__ bq, const float* __restrict__ bk,
              const float* __restrict__ bv,
              __nv_bfloat16* __restrict__ chi, __nv_bfloat16* __restrict__ clo) {
    extern __shared__ char smem[];
    const uint32_t sb = smem_u32(smem);
    const int tid = threadIdx.x, wid = tid >> 5, lane = tid & 31;
    const int z = blockIdx.z, conv = z >> 3;
    const int m0 = blockIdx.y * 128, n0 = blockIdx.x * 128;

    const __nv_bfloat16* Ah = whi + ((size_t)conv * CDIM + m0) * CONVK;
    const __nv_bfloat16* Al = wlo + ((size_t)conv * CDIM + m0) * CONVK;
    const __nv_bfloat16* Ih = ihi + (size_t)z * SPAT * CDIM;
    const __nv_bfloat16* Il = ilo + (size_t)z * SPAT * CDIM;

    const int wm = (wid & 3) * 32, wn = (wid >> 2) * 64;
    const int lrow = lane & 15, lkc = lane >> 4;

    float acc[2][8][4];
    #pragma unroll
    for (int i = 0; i < 2; i++)
        #pragma unroll
        for (int j = 0; j < 8; j++)
            #pragma unroll
            for (int q = 0; q < 4; q++) acc[i][j][q] = 0.f;

    // -------- thread-invariant load precompute --------
    const int arow = tid >> 3, ac = tid & 7;
    // hi/lo source base selection folded once (chunk is thread-constant)
    const __nv_bfloat16* AsrcB = (ac < 4) ? (Ah + ac * 8) : (Al + (ac - 4) * 8);
    const __nv_bfloat16* BsrcB = (ac < 4) ? (Ih + ac * 8) : (Il + (ac - 4) * 8);
    uint32_t offA[4];
    int py[4], px[4];
    #pragma unroll
    for (int p = 0; p < 4; p++) {
        int row = arow + p * 32;
        offA[p] = (uint32_t)row * 128 + ((uint32_t)(ac ^ (row & 7)) << 4);
        int pix = n0 + row;
        py[p] = pix >> 5;
        px[p] = pix & 31;
    }

    auto load_st = [&](uint32_t base, int it, const int* spv, const int* nbv) {
        const int i0 = (it & 31) * 32;
        const size_t aoff = (size_t)it * 32;
        #pragma unroll
        for (int p = 0; p < 4; p++) {
            int row = arow + p * 32;
            cp_async16(base + offA[p], AsrcB + (size_t)row * CONVK + aoff, 16);
        }
        #pragma unroll
        for (int p = 0; p < 4; p++) {
            cp_async16(base + 16384u + offA[p], BsrcB + (size_t)spv[p] * CDIM + i0, nbv[p]);
        }
        CP_COMMIT();
    };

    auto compute_stage = [&](uint32_t sA) {
        const uint32_t sB = sA + 16384;
        #pragma unroll
        for (int ks = 0; ks < 2; ks++) {
            const int ch = ks * 2 + lkc;
            const int cl = 4 + ks * 2 + lkc;
            uint32_t ah[2][4], al[2][4], bfr[4][4];
            #pragma unroll
            for (int mf = 0; mf < 2; mf++) {
                int row = wm + mf * 16 + lrow;
                LDSM_X4(ah[mf], sA + (uint32_t)row * 128 + ((uint32_t)(ch ^ (row & 7)) << 4));
            }
            #pragma unroll
            for (int np = 0; np < 4; np++) {
                int row = wn + np * 16 + lrow;
                LDSM_X4(bfr[np], sB + (uint32_t)row * 128 + ((uint32_t)(ch ^ (row & 7)) << 4));
            }
            #pragma unroll
            for (int mf = 0; mf < 2; mf++)
                #pragma unroll
                for (int np = 0; np < 4; np++) {
                    mma16816(acc[mf][np * 2 + 0], ah[mf], bfr[np][0], bfr[np][2]);
                    mma16816(acc[mf][np * 2 + 1], ah[mf], bfr[np][1], bfr[np][3]);
                }
            #pragma unroll
            for (int mf = 0; mf < 2; mf++) {
                int row = wm + mf * 16 + lrow;
                LDSM_X4(al[mf], sA + (uint32_t)row * 128 + ((uint32_t)(cl ^ (row & 7)) << 4));
            }
            #pragma unroll
            for (int mf = 0; mf < 2; mf++)
                #pragma unroll
                for (int np = 0; np < 4; np++) {
                    mma16816(acc[mf][np * 2 + 0], al[mf], bfr[np][0], bfr[np][2]);
                    mma16816(acc[mf][np * 2 + 1], al[mf], bfr[np][1], bfr[np][3]);
                }
            #pragma unroll
            for (int np = 0; np < 4; np++) {
                int row = wn + np * 16 + lrow;
                LDSM_X4(bfr[np], sB + (uint32_t)row * 128 + ((uint32_t)(cl ^ (row & 7)) << 4));
            }
            #pragma unroll
            for (int mf = 0; mf < 2; mf++)
                #pragma unroll
                for (int np = 0; np < 4; np++) {
                    mma16816(acc[mf][np * 2 + 0], ah[mf], bfr[np][0], bfr[np][2]);
                    mma16816(acc[mf][np * 2 + 1], ah[mf], bfr[np][1], bfr[np][3]);
                }
        }
    };

    // prologue: gather descriptors for phase 0 and first load
    {
        int sp0[4], nb0[4];
        #pragma unroll
        for (int p = 0; p < 4; p++) {
            int y = py[p] - 1, x = px[p] - 1;            // r=0: dy=-1, dx=-1
            bool ok = ((unsigned)y < 32u) && ((unsigned)x < 32u);
            sp0[p] = ok ? (y * 32 + x) : 0;
            nb0[p] = ok ? 16 : 0;
        }
        load_st(sb, 0, sp0, nb0);
    }

    for (int r = 0; r < 9; r++) {
        const int dy = r / 3 - 1, dx = r % 3 - 1;
        const int rn = (r < 8) ? r + 1 : 8;
        const int dyn = rn / 3 - 1, dxn = rn % 3 - 1;
        int sp_c[4], nb_c[4], sp_n[4], nb_n[4];
        #pragma unroll
        for (int p = 0; p < 4; p++) {
            int y = py[p] + dy, x = px[p] + dx;
            bool ok = ((unsigned)y < 32u) && ((unsigned)x < 32u);
            sp_c[p] = ok ? (y * 32 + x) : 0;
            nb_c[p] = ok ? 16 : 0;
            int yn = py[p] + dyn, xn = px[p] + dxn;
            bool okn = ((unsigned)yn < 32u) && ((unsigned)xn < 32u);
            sp_n[p] = okn ? (yn * 32 + xn) : 0;
            nb_n[p] = okn ? 16 : 0;
        }
        #pragma unroll 1
        for (int kk = 0; kk < 32; kk += 2) {
            const int it = r * 32 + kk;
            // even: compute stage0, prefetch it+1 (always same phase) into stage1
            CP_WAIT(0);
            __syncthreads();
            if (it + 1 < CV_NIT) load_st(sb + CV_STAGE, it + 1, sp_c, nb_c);
            else                 CP_COMMIT();
            compute_stage(sb);
            // odd: compute stage1, prefetch it+2 (phase boundary at kk==30) into stage0
            CP_WAIT(0);
            __syncthreads();
            if (it + 2 < CV_NIT) {
                if (kk == 30) load_st(sb, it + 2, sp_n, nb_n);
                else          load_st(sb, it + 2, sp_c, nb_c);
            } else CP_COMMIT();
            compute_stage(sb + CV_STAGE);
        }
    }

    const float* bias = conv == 0 ? bq : (conv == 1 ? bk : bv);
    __nv_bfloat16* oh = chi + (size_t)z * CDIM * SPAT;
    __nv_bfloat16* ol = clo + (size_t)z * CDIM * SPAT;
    #pragma unroll
    for (int mf = 0; mf < 2; mf++) {
        int m = m0 + wm + mf * 16 + (lane >> 2);
        float bi0 = bias[m], bi1 = bias[m + 8];
        #pragma unroll
        for (int nf = 0; nf < 8; nf++) {
            int n = n0 + wn + ((nf >> 1) << 4) + ((nf & 1) << 3) + (lane & 3) * 2;
            split_store2(oh, ol, (size_t)m * SPAT + n, acc[mf][nf][0] + bi0, acc[mf][nf][1] + bi0);
            split_store2(oh, ol, (size_t)(m + 8) * SPAT + n, acc[mf][nf][2] + bi1, acc[mf][nf][3] + bi1);
        }
    }
}

// ---------------- fused flash attention (R7 winner, unchanged) -------------
#define FA_QH 0u
#define FA_QL 16384u
#define FA_K0 32768u
#define FA_VH 98304u
#define FA_VL 114688u
#define FA_PH 131072u
#define FA_PL 163840u
#define FA_RED 196608
#define FA_SMEM 198656

__global__ __launch_bounds__(256)
void flash_attn(const __nv_bfloat16* __restrict__ chi, const __nv_bfloat16* __restrict__ clo,
                const __nv_bfloat16* __restrict__ vthi, const __nv_bfloat16* __restrict__ vtlo,
                const int* __restrict__ mask,
                __nv_bfloat16* __restrict__ aoh, __nv_bfloat16* __restrict__ aol) {
    extern __shared__ char smem[];
    const uint32_t sb = smem_u32(smem);
    float* rmaxp = (float*)(smem + FA_RED);
    float* rsump = (float*)(smem + FA_RED + 1024);
    const int tid = threadIdx.x, wid = tid >> 5, lane = tid & 31;
    const int bh = blockIdx.y, b = bh >> 4, h = bh & 15;
    const int t0 = blockIdx.x * 128;

    const __nv_bfloat16* Qh = chi + (size_t)b * CDIM * SPAT + h * HD;
    const __nv_bfloat16* Ql = clo + (size_t)b * CDIM * SPAT + h * HD;
    const __nv_bfloat16* Kh = chi + (size_t)(8 + b) * CDIM * SPAT + h * HD;
    const __nv_bfloat16* Kl = clo + (size_t)(8 + b) * CDIM * SPAT + h * HD;
    const __nv_bfloat16* Vh = vthi + (size_t)b * SPAT * CDIM + (size_t)(h * HD) * CDIM;
    const __nv_bfloat16* Vl = vtlo + (size_t)b * SPAT * CDIM + (size_t)(h * HD) * CDIM;
    const int* mrow = mask + (size_t)b * CDIM * CDIM;

    const int wm = (wid & 3) * 32;
    const int wn = (wid >> 2) * 64;
    const int wnd = (wid >> 2) * 32;
    const int lrow = lane & 15, lkc = lane >> 4;

    auto load_k = [&](int buf, int s0) {
        uint32_t kh = sb + FA_K0 + (uint32_t)buf * 32768u;
        uint32_t kl = kh + 16384u;
        #pragma unroll
        for (int p = 0; p < 4; p++) {
            int ci = tid + p * 256;
            int row = ci >> 3, c = ci & 7;
            uint32_t off = (uint32_t)row * 128 + ((uint32_t)(c ^ (row & 7)) << 4);
            cp_async16(kh + off, Kh + (size_t)(s0 + row) * SPAT + c * 8, 16);
            cp_async16(kl + off, Kl + (size_t)(s0 + row) * SPAT + c * 8, 16);
        }
    };
    auto load_v = [&](int s0) {
        #pragma unroll
        for (int p = 0; p < 4; p++) {
            int ci = tid + p * 256;
            int row = ci >> 4, cc = ci & 15;
            uint32_t off = (uint32_t)(cc >> 3) * 8192u + (uint32_t)row * 128 +
                           ((uint32_t)((cc & 7) ^ (row & 7)) << 4);
            cp_async16(sb + FA_VH + off, Vh + (size_t)row * CDIM + s0 + cc * 8, 16);
            cp_async16(sb + FA_VL + off, Vl + (size_t)row * CDIM + s0 + cc * 8, 16);
        }
    };

    #pragma unroll
    for (int p = 0; p < 4; p++) {
        int ci = tid + p * 256;
        int row = ci >> 3, c = ci & 7;
        uint32_t off = (uint32_t)row * 128 + ((uint32_t)(c ^ (row & 7)) << 4);
        cp_async16(sb + FA_QH + off, Qh + (size_t)(t0 + row) * SPAT + c * 8, 16);
        cp_async16(sb + FA_QL + off, Ql + (size_t)(t0 + row) * SPAT + c * 8, 16);
    }
    load_k(0, 0);
    CP_COMMIT();

    float m_s[4], l_s[4];
    #pragma unroll
    for (int rs = 0; rs < 4; rs++) { m_s[rs] = -3e38f; l_s[rs] = 0.f; }
    float acc_o[2][4][4];
    #pragma unroll
    for (int i = 0; i < 2; i++)
        #pragma unroll
        for (int j = 0; j < 4; j++)
            #pragma unroll
            for (int q = 0; q < 4; q++) acc_o[i][j][q] = 0.f;

    for (int it = 0; it < 8; it++) {
        const int s0 = it * 128;
        CP_WAIT(0);
        __syncthreads();
        load_v(s0); CP_COMMIT();

        float accS[2][8][4];
        #pragma unroll
        for (int i = 0; i < 2; i++)
            #pragma unroll
            for (int j = 0; j < 8; j++)
                #pragma unroll
                for (int q = 0; q < 4; q++) accS[i][j][q] = 0.f;
        {
            const uint32_t sAh = sb + FA_QH, sAl = sb + FA_QL;
            const uint32_t sBh = sb + FA_K0 + (uint32_t)(it & 1) * 32768u;
            const uint32_t sBl = sBh + 16384u;
            #pragma unroll
            for (int ks = 0; ks < 4; ks++) {
                const int kc = ks * 2 + lkc;
                uint32_t ah[2][4], al[2][4], bfr[4][4];
                #pragma unroll
                for (int mf = 0; mf < 2; mf++) {
                    int row = wm + mf * 16 + lrow;
                    LDSM_X4(ah[mf], sAh + (uint32_t)row * 128 + ((uint32_t)(kc ^ (row & 7)) << 4));
                }
                #pragma unroll
                for (int np = 0; np < 4; np++) {
                    int row = wn + np * 16 + lrow;
                    LDSM_X4(bfr[np], sBh + (uint32_t)row * 128 + ((uint32_t)(kc ^ (row & 7)) << 4));
                }
                #pragma unroll
                for (int mf = 0; mf < 2; mf++)
                    #pragma unroll
                    for (int np = 0; np < 4; np++) {
                        mma16816(accS[mf][np * 2 + 0], ah[mf], bfr[np][0], bfr[np][2]);
                        mma16816(accS[mf][np * 2 + 1], ah[mf], bfr[np][1], bfr[np][3]);
                    }
                #pragma unroll
                for (int mf = 0; mf < 2; mf++) {
                    int row = wm + mf * 16 + lrow;
                    LDSM_X4(al[mf], sAl + (uint32_t)row * 128 + ((uint32_t)(kc ^ (row & 7)) << 4));
                }
                #pragma unroll
                for (int mf = 0; mf < 2; mf++)
                    #pragma unroll
                    for (int np = 0; np < 4; np++) {
                        mma16816(accS[mf][np * 2 + 0], al[mf], bfr[np][0], bfr[np][2]);
                        mma16816(accS[mf][np * 2 + 1], al[mf], bfr[np][1], bfr[np][3]);
                    }
                #pragma unroll
                for (int np = 0; np < 4; np++) {
                    int row = wn + np * 16 + lrow;
                    LDSM_X4(bfr[np], sBl + (uint32_t)row * 128 + ((uint32_t)(kc ^ (row & 7)) << 4));
                }
                #pragma unroll
                for (int mf = 0; mf < 2; mf++)
                    #pragma unroll
                    for (int np = 0; np < 4; np++) {
                        mma16816(accS[mf][np * 2 + 0], ah[mf], bfr[np][0], bfr[np][2]);
                        mma16816(accS[mf][np * 2 + 1], ah[mf], bfr[np][1], bfr[np][3]);
                    }
            }
        }

        if (it + 1 < 8) load_k((it + 1) & 1, s0 + 128);
        CP_COMMIT();

        #pragma unroll
        for (int mf = 0; mf < 2; mf++) {
            int t = t0 + wm + mf * 16 + (lane >> 2);
            #pragma unroll
            for (int nf = 0; nf < 8; nf++) {
                int n = s0 + wn + ((nf >> 1) << 4) + ((nf & 1) << 3) + (lane & 3) * 2;
                int2 m0v = *(const int2*)(mrow + (size_t)t * CDIM + n);
                int2 m1v = *(const int2*)(mrow + (size_t)(t + 8) * CDIM + n);
                accS[mf][nf][0] = m0v.x ? accS[mf][nf][0] * 0.125f : -1e9f;
                accS[mf][nf][1] = m0v.y ? accS[mf][nf][1] * 0.125f : -1e9f;
                accS[mf][nf][2] = m1v.x ? accS[mf][nf][2] * 0.125f : -1e9f;
                accS[mf][nf][3] = m1v.y ? accS[mf][nf][3] * 0.125f : -1e9f;
            }
        }

        float lm[4];
        #pragma unroll
        for (int rs = 0; rs < 4; rs++) lm[rs] = -3e38f;
        #pragma unroll
        for (int mf = 0; mf < 2; mf++)
            #pragma unroll
            for (int nf = 0; nf < 8; nf++) {
                lm[mf * 2 + 0] = fmaxf(lm[mf * 2 + 0], fmaxf(accS[mf][nf][0], accS[mf][nf][1]));
                lm[mf * 2 + 1] = fmaxf(lm[mf * 2 + 1], fmaxf(accS[mf][nf][2], accS[mf][nf][3]));
            }
        #pragma unroll
        for (int rs = 0; rs < 4; rs++) {
            lm[rs] = fmaxf(lm[rs], __shfl_xor_sync(0xffffffffu, lm[rs], 1));
            lm[rs] = fmaxf(lm[rs], __shfl_xor_sync(0xffffffffu, lm[rs], 2));
        }
        if ((lane & 3) == 0) {
            #pragma unroll
            for (int rs = 0; rs < 4; rs++) {
                int row = wm + (rs >> 1) * 16 + (lane >> 2) + (rs & 1) * 8;
                rmaxp[(wid >> 2) * 128 + row] = lm[rs];
            }
        }
        __syncthreads();

        float fac[4], mnew[4];
        #pragma unroll
        for (int rs = 0; rs < 4; rs++) {
            int row = wm + (rs >> 1) * 16 + (lane >> 2) + (rs & 1) * 8;
            float cm = fmaxf(rmaxp[row], rmaxp[128 + row]);
            mnew[rs] = fmaxf(m_s[rs], cm);
            fac[rs] = __expf(m_s[rs] - mnew[rs]);
            m_s[rs] = mnew[rs];
        }

        float ls[4];
        #pragma unroll
        for (int rs = 0; rs < 4; rs++) ls[rs] = 0.f;
        #pragma unroll
        for (int mf = 0; mf < 2; mf++) {
            int row0 = wm + mf * 16 + (lane >> 2);
            #pragma unroll
            for (int nf = 0; nf < 8; nf++) {
                int sc = wn + ((nf >> 1) << 4) + ((nf & 1) << 3) + (lane & 3) * 2;
                float p0 = __expf(accS[mf][nf][0] - mnew[mf * 2 + 0]);
                float p1 = __expf(accS[mf][nf][1] - mnew[mf * 2 + 0]);
                float p2 = __expf(accS[mf][nf][2] - mnew[mf * 2 + 1]);
                float p3 = __expf(accS[mf][nf][3] - mnew[mf * 2 + 1]);
                ls[mf * 2 + 0] += p0 + p1;
                ls[mf * 2 + 1] += p2 + p3;
                int sub = sc >> 6, scc = sc & 63;
                uint32_t boff = (uint32_t)sub * 16384u +
                                (((uint32_t)(scc >> 3) ^ ((uint32_t)row0 & 7)) << 4) + (scc & 7) * 2;
                uint32_t boff1 = (uint32_t)sub * 16384u +
                                 (((uint32_t)(scc >> 3) ^ ((uint32_t)(row0 + 8) & 7)) << 4) + (scc & 7) * 2;
                __nv_bfloat16 h0 = __float2bfloat16(p0), h1 = __float2bfloat16(p1);
                __nv_bfloat162 hv; hv.x = h0; hv.y = h1;
                *(__nv_bfloat162*)(smem + FA_PH + (uint32_t)row0 * 128 + boff) = hv;
                __nv_bfloat162 lv;
                lv.x = __float2bfloat16(p0 - __bfloat162float(h0));
                lv.y = __float2bfloat16(p1 - __bfloat162float(h1));
                *(__nv_bfloat162*)(smem + FA_PL + (uint32_t)row0 * 128 + boff) = lv;
                __nv_bfloat16 h2 = __float2bfloat16(p2), h3 = __float2bfloat16(p3);
                __nv_bfloat162 hv2; hv2.x = h2; hv2.y = h3;
                *(__nv_bfloat162*)(smem + FA_PH + (uint32_t)(row0 + 8) * 128 + boff1) = hv2;
                __nv_bfloat162 lv2;
                lv2.x = __float2bfloat16(p2 - __bfloat162float(h2));
                lv2.y = __float2bfloat16(p3 - __bfloat162float(h3));
                *(__nv_bfloat162*)(smem + FA_PL + (uint32_t)(row0 + 8) * 128 + boff1) = lv2;
            }
        }
        #pragma unroll
        for (int rs = 0; rs < 4; rs++) {
            ls[rs] += __shfl_xor_sync(0xffffffffu, ls[rs], 1);
            ls[rs] += __shfl_xor_sync(0xffffffffu, ls[rs], 2);
        }
        if ((lane & 3) == 0) {
            #pragma unroll
            for (int rs = 0; rs < 4; rs++) {
                int row = wm + (rs >> 1) * 16 + (lane >> 2) + (rs & 1) * 8;
                rsump[(wid >> 2) * 128 + row] = ls[rs];
            }
        }
        CP_WAIT(1);
        __syncthreads();

        #pragma unroll
        for (int rs = 0; rs < 4; rs++) {
            int row = wm + (rs >> 1) * 16 + (lane >> 2) + (rs & 1) * 8;
            float cs = rsump[row] + rsump[128 + row];
            l_s[rs] = l_s[rs] * fac[rs] + cs;
        }
        #pragma unroll
        for (int mf = 0; mf < 2; mf++)
            #pragma unroll
            for (int nf = 0; nf < 4; nf++) {
                acc_o[mf][nf][0] *= fac[mf * 2 + 0];
                acc_o[mf][nf][1] *= fac[mf * 2 + 0];
                acc_o[mf][nf][2] *= fac[mf * 2 + 1];
                acc_o[mf][nf][3] *= fac[mf * 2 + 1];
            }

        #pragma unroll
        for (int ksi = 0; ksi < 8; ksi++) {
            const int cc = ksi * 2 + lkc;
            const int sub = cc >> 3, c = cc & 7;
            uint32_t ph[2][4], pl[2][4], vfh[2][4], vfl[2][4];
            #pragma unroll
            for (int mf = 0; mf < 2; mf++) {
                int row = wm + mf * 16 + lrow;
                uint32_t off = (uint32_t)sub * 16384u + (uint32_t)row * 128 +
                               ((uint32_t)(c ^ (row & 7)) << 4);
                LDSM_X4(ph[mf], sb + FA_PH + off);
                LDSM_X4(pl[mf], sb + FA_PL + off);
            }
            #pragma unroll
            for (int np = 0; np < 2; np++) {
                int row = wnd + np * 16 + lrow;
                uint32_t off = (uint32_t)sub * 8192u + (uint32_t)row * 128 +
                               ((uint32_t)(c ^ (row & 7)) << 4);
                LDSM_X4(vfh[np], sb + FA_VH + off);
                LDSM_X4(vfl[np], sb + FA_VL + off);
            }
            #pragma unroll
            for (int mf = 0; mf < 2; mf++)
                #pragma unroll
                for (int np = 0; np < 2; np++) {
                    mma16816(acc_o[mf][np * 2 + 0], ph[mf], vfh[np][0], vfh[np][2]);
                    mma16816(acc_o[mf][np * 2 + 1], ph[mf], vfh[np][1], vfh[np][3]);
                    mma16816(acc_o[mf][np * 2 + 0], pl[mf], vfh[np][0], vfh[np][2]);
                    mma16816(acc_o[mf][np * 2 + 1], pl[mf], vfh[np][1], vfh[np][3]);
                    mma16816(acc_o[mf][np * 2 + 0], ph[mf], vfl[np][0], vfl[np][2]);
                    mma16816(acc_o[mf][np * 2 + 1], ph[mf], vfl[np][1], vfl[np][3]);
                }
        }
    }

    float invl[4];
    #pragma unroll
    for (int rs = 0; rs < 4; rs++) invl[rs] = 1.0f / l_s[rs];
    #pragma unroll
    for (int mf = 0; mf < 2; mf++) {
        int t = t0 + wm + mf * 16 + (lane >> 2);
        #pragma unroll
        for (int nf = 0; nf < 4; nf++) {
            int n = h * HD + wnd + ((nf >> 1) << 4) + ((nf & 1) << 3) + (lane & 3) * 2;
            split_store2(aoh, aol, ((size_t)b * CDIM + t) * SPAT + n,
                         acc_o[mf][nf][0] * invl[mf * 2 + 0],
                         acc_o[mf][nf][1] * invl[mf * 2 + 0]);
            split_store2(aoh, aol, ((size_t)b * CDIM + t + 8) * SPAT + n,
                         acc_o[mf][nf][2] * invl[mf * 2 + 1],
                         acc_o[mf][nf][3] * invl[mf * 2 + 1]);
        }
    }
}

// ---------------- output projection via MMA, 2-stage pipeline --------------
#define PJ_STAGE 65536
__global__ __launch_bounds__(256)
void proj_mma(const __nv_bfloat16* __restrict__ aoh, const __nv_bfloat16* __restrict__ aol,
              const __nv_bfloat16* __restrict__ woh, const __nv_bfloat16* __restrict__ wol,
              const float* __restrict__ bo, float* __restrict__ out) {
    extern __shared__ char smem[];
    const uint32_t sb = smem_u32(smem);
    const int tid = threadIdx.x, wid = tid >> 5, lane = tid & 31;
    const int row0 = blockIdx.y * 128, m0 = blockIdx.x * 128;

    const __nv_bfloat16* Ah = aoh + (size_t)row0 * CDIM;
    const __nv_bfloat16* Al = aol + (size_t)row0 * CDIM;
    const __nv_bfloat16* Bh = woh + (size_t)m0 * CDIM;
    const __nv_bfloat16* Bl = wol + (size_t)m0 * CDIM;

    const int wm = (wid & 3) * 32, wn = (wid >> 2) * 64;
    const int lrow = lane & 15, lkc = lane >> 4;

    float acc[2][8][4];
    #pragma unroll
    for (int i = 0; i < 2; i++)
        #pragma unroll
        for (int j = 0; j < 8; j++)
            #pragma unroll
            for (int q = 0; q < 4; q++) acc[i][j][q] = 0.f;

    auto load_stage = [&](int s, int it) {
        uint32_t base = sb + s * PJ_STAGE;
        #pragma unroll
        for (int p = 0; p < 4; p++) {
            int ci = tid + p * 256;
            int row = ci >> 3, c = ci & 7;
            uint32_t off = (uint32_t)row * 128 + ((uint32_t)(c ^ (row & 7)) << 4);
            cp_async16(base + off, Ah + (size_t)row * CDIM + it * 64 + c * 8, 16);
            cp_async16(base + 16384 + off, Al + (size_t)row * CDIM + it * 64 + c * 8, 16);
            cp_async16(base + 32768 + off, Bh + (size_t)row * CDIM + it * 64 + c * 8, 16);
            cp_async16(base + 49152 + off, Bl + (size_t)row * CDIM + it * 64 + c * 8, 16);
        }
        CP_COMMIT();
    };

    load_stage(0, 0);
    for (int it = 0; it < 16; it++) {
        int s = it & 1;
        if (it + 1 < 16) { load_stage(s ^ 1, it + 1); CP_WAIT(1); }
        else             { CP_WAIT(0); }
        __syncthreads();

        const uint32_t sAh = sb + s * PJ_STAGE;
        const uint32_t sAl = sAh + 16384, sBh = sAh + 32768, sBl = sAh + 49152;
        #pragma unroll
        for (int ks = 0; ks < 4; ks++) {
            const int kc = ks * 2 + lkc;
            uint32_t ah[2][4], al[2][4], bfr[4][4];
            #pragma unroll
            for (int mf = 0; mf < 2; mf++) {
                int row = wm + mf * 16 + lrow;
                LDSM_X4(ah[mf], sAh + (uint32_t)row * 128 + ((uint32_t)(kc ^ (row & 7)) << 4));
            }
            #pragma unroll
            for (int np = 0; np < 4; np++) {
                int row = wn + np * 16 + lrow;
                LDSM_X4(bfr[np], sBh + (uint32_t)row * 128 + ((uint32_t)(kc ^ (row & 7)) << 4));
            }
            #pragma unroll
            for (int mf = 0; mf < 2; mf++)
                #pragma unroll
                for (int np = 0; np < 4; np++) {
                    mma16816(acc[mf][np * 2 + 0], ah[mf], bfr[np][0], bfr[np][2]);
                    mma16816(acc[mf][np * 2 + 1], ah[mf], bfr[np][1], bfr[np][3]);
                }
            #pragma unroll
            for (int mf = 0; mf < 2; mf++) {
                int row = wm + mf * 16 + lrow;
                LDSM_X4(al[mf], sAl + (uint32_t)row * 128 + ((uint32_t)(kc ^ (row & 7)) << 4));
            }
            #pragma unroll
            for (int mf = 0; mf < 2; mf++)
                #pragma unroll
                for (int np = 0; np < 4; np++) {
                    mma16816(acc[mf][np * 2 + 0], al[mf], bfr[np][0], bfr[np][2]);
                    mma16816(acc[mf][np * 2 + 1], al[mf], bfr[np][1], bfr[np][3]);
                }
            #pragma unroll
            for (int np = 0; np < 4; np++) {
                int row = wn + np * 16 + lrow;
                LDSM_X4(bfr[np], sBl + (uint32_t)row * 128 + ((uint32_t)(kc ^ (row & 7)) << 4));
            }
            #pragma unroll
            for (int mf = 0; mf < 2; mf++)
                #pragma unroll
                for (int np = 0; np < 4; np++) {
                    mma16816(acc[mf][np * 2 + 0], ah[mf], bfr[np][0], bfr[np][2]);
                    mma16816(acc[mf][np * 2 + 1], ah[mf], bfr[np][1], bfr[np][3]);
                }
        }
        __syncthreads();
    }

    #pragma unroll
    for (int mf = 0; mf < 2; mf++) {
        int r = row0 + wm + mf * 16 + (lane >> 2);
        #pragma unroll
        for (int nf = 0; nf < 8; nf++) {
            int n = m0 + wn + ((nf >> 1) << 4) + ((nf & 1) << 3) + (lane & 3) * 2;
            float b0 = bo[n], b1 = bo[n + 1];
            float2 v0 = {acc[mf][nf][0] + b0, acc[mf][nf][1] + b1};
            float2 v1 = {acc[mf][nf][2] + b0, acc[mf][nf][3] + b1};
            *(float2*)(out + (size_t)r * CDIM + n) = v0;
            *(float2*)(out + (size_t)(r + 8) * CDIM + n) = v1;
        }
    }
}

// ---------------- launch ---------------------------------------------------
extern "C" void kernel_launch(void* const* d_in, const int* in_sizes, int n_in,
                              void* d_out, int out_size) {
    const float* q  = (const float*)d_in[0];
    const float* k  = (const float*)d_in[1];
    const float* v  = (const float*)d_in[2];
    const float* Wq = (const float*)d_in[3];
    const float* bq = (const float*)d_in[4];
    const float* Wk = (const float*)d_in[5];
    const float* bk = (const float*)d_in[6];
    const float* Wv = (const float*)d_in[7];
    const float* bv = (const float*)d_in[8];
    const float* Wo = (const float*)d_in[9];
    const float* bo = (const float*)d_in[10];
    const int*   mask = (const int*)d_in[11];
    float* out = (float*)d_out;

    __nv_bfloat16 *whi, *wlo, *ihi, *ilo, *chi, *clo, *vthi, *vtlo;
    __nv_bfloat16 *wohi, *wolo, *aoh, *aol;
    cudaGetSymbolAddress((void**)&whi, g_whi);
    cudaGetSymbolAddress((void**)&wlo, g_wlo);
    cudaGetSymbolAddress((void**)&ihi, g_ihi);
    cudaGetSymbolAddress((void**)&ilo, g_ilo);
    cudaGetSymbolAddress((void**)&chi, g_chi);
    cudaGetSymbolAddress((void**)&clo, g_clo);
    cudaGetSymbolAddress((void**)&vthi, g_vthi);
    cudaGetSymbolAddress((void**)&vtlo, g_vtlo);
    cudaGetSymbolAddress((void**)&wohi, g_wohi);
    cudaGetSymbolAddress((void**)&wolo, g_wolo);
    cudaGetSymbolAddress((void**)&aoh, g_aohi);
    cudaGetSymbolAddress((void**)&aol, g_aolo);

    cudaFuncSetAttribute(conv_mma,   cudaFuncAttributeMaxDynamicSharedMemorySize, 2 * CV_STAGE);
    cudaFuncSetAttribute(flash_attn, cudaFuncAttributeMaxDynamicSharedMemorySize, FA_SMEM);
    cudaFuncSetAttribute(proj_mma,   cudaFuncAttributeMaxDynamicSharedMemorySize, 2 * PJ_STAGE);

    split_w<<<dim3(CDIM, 3), 256>>>(Wq, Wk, Wv, whi, wlo);
    split_wo<<<4096, 256>>>(Wo, wohi, wolo);
    transpose_split_in<<<dim3(32, 32, 24), dim3(32, 8)>>>(q, k, v, ihi, ilo);

    conv_mma<<<dim3(8, 8, 24), 256, 2 * CV_STAGE>>>(whi, wlo, ihi, ilo, bq, bk, bv, chi, clo);

    tr_bf16<<<dim3(32, 32, 8), dim3(32, 8)>>>(chi + (size_t)16 * CDIM * SPAT, vthi);
    tr_bf16<<<dim3(32, 32, 8), dim3(32, 8)>>>(clo + (size_t)16 * CDIM * SPAT, vtlo);

    flash_attn<<<dim3(8, BATCH * NH), 256, FA_SMEM>>>(chi, clo, vthi, vtlo, mask, aoh, aol);

    proj_mma<<<dim3(8, 64), 256, 2 * PJ_STAGE>>>(aoh, aol, wohi, wolo, bo, out);
}

// round 12
// speedup vs baseline: 1.4697x; 1.4697x over previous
#include <cuda_runtime.h>
#include <cuda_fp16.h>
#include <cstdint>
#include <math.h>

// Shapes
#define BATCH 8
#define CDIM  1024      // channels == tokens
#define SPAT  1024      // 32*32 spatial
#define NH    16
#define HD    64
#define CONVK 9216      // 1024*9

// ---------------- scratch (device globals) ---------------------------------
__device__ __half g_whi[(size_t)3 * CDIM * CONVK];   // conv A hi [conv][o][k]
__device__ __half g_wlo[(size_t)3 * CDIM * CONVK];   // conv A lo
__device__ __half g_in[(size_t)24 * SPAT * CDIM];    // conv B single [z][pix][i]
__device__ __half g_qhi[(size_t)BATCH * CDIM * SPAT]; // Q hi [b][t][d]
__device__ __half g_qlo[(size_t)BATCH * CDIM * SPAT];
__device__ __half g_k[(size_t)BATCH * CDIM * SPAT];   // K single [b][s][d]
__device__ __half g_v[(size_t)BATCH * CDIM * SPAT];   // V single [b][s][d]
__device__ __half g_vt[(size_t)BATCH * SPAT * CDIM];  // V^T single [b][d][s]
__device__ __half g_wo[(size_t)CDIM * CDIM];          // Wo single [m][k]
__device__ __half g_aohi[(size_t)BATCH * CDIM * SPAT];
__device__ __half g_aolo[(size_t)BATCH * CDIM * SPAT];

// ---------------- PTX helpers (sm_80-baseline only) ------------------------
__device__ __forceinline__ uint32_t smem_u32(const void* p) {
    uint32_t a;
    asm("{ .reg .u64 t; cvta.to.shared.u64 t, %1; cvt.u32.u64 %0, t; }" : "=r"(a) : "l"(p));
    return a;
}
__device__ __forceinline__ void cp_async16(uint32_t dst, const void* src, int src_bytes) {
    asm volatile("cp.async.cg.shared.global [%0], [%1], 16, %2;"
                 :: "r"(dst), "l"(src), "r"(src_bytes) : "memory");
}
#define CP_COMMIT() asm volatile("cp.async.commit_group;" ::: "memory")
#define CP_WAIT(n)  asm volatile("cp.async.wait_group %0;" :: "n"(n) : "memory")

#define LDSM_X4(r, a) \
    asm volatile("ldmatrix.sync.aligned.m8n8.x4.shared.b16 {%0,%1,%2,%3}, [%4];" \
                 : "=r"((r)[0]), "=r"((r)[1]), "=r"((r)[2]), "=r"((r)[3]) : "r"(a))

__device__ __forceinline__ void mma16816(float* c, const uint32_t* a, uint32_t b0, uint32_t b1) {
    asm volatile("mma.sync.aligned.m16n8k16.row.col.f32.f16.f16.f32 "
                 "{%0,%1,%2,%3},{%4,%5,%6,%7},{%8,%9},{%0,%1,%2,%3};"
                 : "+f"(c[0]), "+f"(c[1]), "+f"(c[2]), "+f"(c[3])
                 : "r"(a[0]), "r"(a[1]), "r"(a[2]), "r"(a[3]), "r"(b0), "r"(b1));
}

__device__ __forceinline__ void hsplit_store2(__half* hi, __half* lo,
                                              size_t idx, float a, float b) {
    __half ha = __float2half(a), hb = __float2half(b);
    *(__half2*)(hi + idx) = __halves2half2(ha, hb);
    *(__half2*)(lo + idx) = __halves2half2(__float2half(a - __half2float(ha)),
                                           __float2half(b - __half2float(hb)));
}
__device__ __forceinline__ void hstore2(__half* o, size_t idx, float a, float b) {
    *(__half2*)(o + idx) = __floats2half2_rn(a, b);
}

// ---------------- precompute: weight split to [o][r*1024+i] ----------------
__global__ void split_w(const float* __restrict__ Wq, const float* __restrict__ Wk,
                        const float* __restrict__ Wv,
                        __half* __restrict__ hi, __half* __restrict__ lo) {
    const int o = blockIdx.x, conv = blockIdx.y;
    const float* W = (conv == 0 ? Wq : (conv == 1 ? Wk : Wv)) + (size_t)o * CONVK;
    size_t ob = ((size_t)conv * CDIM + o) * CONVK;
    for (int kk = threadIdx.x; kk < CONVK; kk += 256) {
        int r = kk >> 10, i = kk & 1023;
        float w = W[i * 9 + r];
        __half h = __float2half(w);
        hi[ob + kk] = h;
        lo[ob + kk] = __float2half(w - __half2float(h));
    }
}

__global__ void wo_half(const float* __restrict__ Wo, __half* __restrict__ o) {
    int idx = blockIdx.x * 256 + threadIdx.x;
    o[idx] = __float2half(Wo[idx]);
}

// ---------------- precompute: transpose inputs to fp16 single --------------
__global__ void transpose_in(const float* __restrict__ q, const float* __restrict__ k,
                             const float* __restrict__ v, __half* __restrict__ out) {
    __shared__ float t[32][33];
    const int z = blockIdx.z, conv = z >> 3, b = z & 7;
    const float* src = (conv == 0 ? q : (conv == 1 ? k : v)) + (size_t)b * CDIM * SPAT;
    const int i0 = blockIdx.y * 32, p0 = blockIdx.x * 32;
    const int tx = threadIdx.x, ty = threadIdx.y;
    #pragma unroll
    for (int r = ty; r < 32; r += 8) t[r][tx] = src[(size_t)(i0 + r) * SPAT + p0 + tx];
    __syncthreads();
    size_t base = (size_t)z * SPAT * CDIM;
    #pragma unroll
    for (int r = ty; r < 32; r += 8)
        out[base + (size_t)(p0 + r) * CDIM + i0 + tx] = __float2half(t[tx][r]);
}

// ---------------- fp16 transpose (V -> V^T) --------------------------------
__global__ void tr_half(const __half* __restrict__ in, __half* __restrict__ out) {
    __shared__ __half t[32][33];
    const int b = blockIdx.z, s0 = blockIdx.y * 32, d0 = blockIdx.x * 32;
    const __half* ip = in + (size_t)b * CDIM * SPAT;
    __half* op = out + (size_t)b * CDIM * SPAT;
    const int tx = threadIdx.x, ty = threadIdx.y;
    #pragma unroll
    for (int r = ty; r < 32; r += 8) t[r][tx] = ip[(size_t)(s0 + r) * SPAT + d0 + tx];
    __syncthreads();
    #pragma unroll
    for (int r = ty; r < 32; r += 8) op[(size_t)(d0 + r) * CDIM + s0 + tx] = t[tx][r];
}

// ---------------- conv via warp MMA: 128x128, BK=64, fp16 2-term -----------
// Stage (48KB): Ahi[128][64] @0 | Alo @16384 | B[128][64] @32768
// (128B rows, c^(row&7) swizzle). 2 stages, unroll x2 (R10 loop structure).
#define CV_STAGE 49152
#define CV_NIT   144    // 9216/64

__global__ __launch_bounds__(256, 2)
void conv_mma(const __half* __restrict__ whi, const __half* __restrict__ wlo,
              const __half* __restrict__ gin,
              const float* __restrict__ bq, const float* __restrict__ bk,
              const float* __restrict__ bv,
              __half* __restrict__ qhi, __half* __restrict__ qlo,
              __half* __restrict__ kout, __half* __restrict__ vout) {
    extern __shared__ char smem[];
    const uint32_t sb = smem_u32(smem);
    const int tid = threadIdx.x, wid = tid >> 5, lane = tid & 31;
    const int z = blockIdx.z, conv = z >> 3, b = z & 7;
    const int m0 = blockIdx.y * 128, n0 = blockIdx.x * 128;

    const __half* Ah = whi + ((size_t)conv * CDIM + m0) * CONVK;
    const __half* Al = wlo + ((size_t)conv * CDIM + m0) * CONVK;
    const __half* In = gin + (size_t)z * SPAT * CDIM;

    const int wm = (wid & 3) * 32, wn = (wid >> 2) * 64;
    const int lrow = lane & 15, lkc = lane >> 4;

    float acc[2][8][4];
    #pragma unroll
    for (int i = 0; i < 2; i++)
        #pragma unroll
        for (int j = 0; j < 8; j++)
            #pragma unroll
            for (int q = 0; q < 4; q++) acc[i][j][q] = 0.f;

    const int arow = tid >> 3, ac = tid & 7;

    auto load_stage = [&](uint32_t base, int it) {
        const int r = it >> 4;
        const int dy = r / 3 - 1, dx = r % 3 - 1;
        const int i0 = (it & 15) * 64;
        #pragma unroll
        for (int p = 0; p < 4; p++) {
            int row = arow + p * 32;
            uint32_t dst = base + (uint32_t)row * 128 + ((uint32_t)(ac ^ (row & 7)) << 4);
            const __half* asrc = Ah + (size_t)row * CONVK + it * 64 + ac * 8;
            const __half* lsrc = Al + (size_t)row * CONVK + it * 64 + ac * 8;
            cp_async16(dst, asrc, 16);
            cp_async16(dst + 16384u, lsrc, 16);
        }
        #pragma unroll
        for (int p = 0; p < 4; p++) {
            int row = arow + p * 32;
            int pix = n0 + row;
            int y = (pix >> 5) + dy, x = (pix & 31) + dx;
            bool ok = ((unsigned)y < 32u) && ((unsigned)x < 32u);
            int sp = ok ? (y * 32 + x) : 0;
            int nb = ok ? 16 : 0;
            uint32_t dst = base + 32768u + (uint32_t)row * 128 + ((uint32_t)(ac ^ (row & 7)) << 4);
            cp_async16(dst, In + (size_t)sp * CDIM + i0 + ac * 8, nb);
        }
        CP_COMMIT();
    };

    auto compute_stage = [&](uint32_t sA) {
        const uint32_t sAl = sA + 16384u, sB = sA + 32768u;
        #pragma unroll
        for (int ks = 0; ks < 4; ks++) {
            const int kc = ks * 2 + lkc;
            uint32_t ah[2][4], al[2][4], bfr[4][4];
            #pragma unroll
            for (int mf = 0; mf < 2; mf++) {
                int row = wm + mf * 16 + lrow;
                LDSM_X4(ah[mf], sA + (uint32_t)row * 128 + ((uint32_t)(kc ^ (row & 7)) << 4));
            }
            #pragma unroll
            for (int np = 0; np < 4; np++) {
                int row = wn + np * 16 + lrow;
                LDSM_X4(bfr[np], sB + (uint32_t)row * 128 + ((uint32_t)(kc ^ (row & 7)) << 4));
            }
            #pragma unroll
            for (int mf = 0; mf < 2; mf++)
                #pragma unroll
                for (int np = 0; np < 4; np++) {
                    mma16816(acc[mf][np * 2 + 0], ah[mf], bfr[np][0], bfr[np][2]);
                    mma16816(acc[mf][np * 2 + 1], ah[mf], bfr[np][1], bfr[np][3]);
                }
            #pragma unroll
            for (int mf = 0; mf < 2; mf++) {
                int row = wm + mf * 16 + lrow;
                LDSM_X4(al[mf], sAl + (uint32_t)row * 128 + ((uint32_t)(kc ^ (row & 7)) << 4));
            }
            #pragma unroll
            for (int mf = 0; mf < 2; mf++)
                #pragma unroll
                for (int np = 0; np < 4; np++) {
                    mma16816(acc[mf][np * 2 + 0], al[mf], bfr[np][0], bfr[np][2]);
                    mma16816(acc[mf][np * 2 + 1], al[mf], bfr[np][1], bfr[np][3]);
                }
        }
    };

    load_stage(sb, 0);

    for (int it = 0; it < CV_NIT; it += 2) {
        CP_WAIT(0);
        __syncthreads();
        if (it + 1 < CV_NIT) load_stage(sb + CV_STAGE, it + 1);
        compute_stage(sb);
        CP_WAIT(0);
        __syncthreads();
        if (it + 2 < CV_NIT) load_stage(sb, it + 2);
        compute_stage(sb + CV_STAGE);
    }

    const float* bias = conv == 0 ? bq : (conv == 1 ? bk : bv);
    #pragma unroll
    for (int mf = 0; mf < 2; mf++) {
        int m = m0 + wm + mf * 16 + (lane >> 2);
        float bi0 = bias[m], bi1 = bias[m + 8];
        #pragma unroll
        for (int nf = 0; nf < 8; nf++) {
            int n = n0 + wn + ((nf >> 1) << 4) + ((nf & 1) << 3) + (lane & 3) * 2;
            size_t i0 = ((size_t)b * CDIM + m) * SPAT + n;
            size_t i1 = ((size_t)b * CDIM + m + 8) * SPAT + n;
            float a0 = acc[mf][nf][0] + bi0, a1 = acc[mf][nf][1] + bi0;
            float a2 = acc[mf][nf][2] + bi1, a3 = acc[mf][nf][3] + bi1;
            if (conv == 0) {
                hsplit_store2(qhi, qlo, i0, a0, a1);
                hsplit_store2(qhi, qlo, i1, a2, a3);
            } else if (conv == 1) {
                hstore2(kout, i0, a0, a1);
                hstore2(kout, i1, a2, a3);
            } else {
                hstore2(vout, i0, a0, a1);
                hstore2(vout, i1, a2, a3);
            }
        }
    }
}

// ---------------- fused flash attention, fp16 2-term -----------------------
// smem: Qhi 16K @0 | Qlo 16K @16384 | K dbuf 2x16K @32768 |
//       V 16K @65536 (2 subtiles 8K) | Ph 32K @81920 | Pl 32K @114688 | red @147456
#define FA_QH 0u
#define FA_QL 16384u
#define FA_K0 32768u
#define FA_V  65536u
#define FA_PH 81920u
#define FA_PL 114688u
#define FA_RED 147456
#define FA_SMEM 149504

__global__ __launch_bounds__(256)
void flash_attn(const __half* __restrict__ qhi, const __half* __restrict__ qlo,
                const __half* __restrict__ kin, const __half* __restrict__ vt,
                const int* __restrict__ mask,
                __half* __restrict__ aoh, __half* __restrict__ aol) {
    extern __shared__ char smem[];
    const uint32_t sb = smem_u32(smem);
    float* rmaxp = (float*)(smem + FA_RED);
    float* rsump = (float*)(smem + FA_RED + 1024);
    const int tid = threadIdx.x, wid = tid >> 5, lane = tid & 31;
    const int bh = blockIdx.y, b = bh >> 4, h = bh & 15;
    const int t0 = blockIdx.x * 128;

    const __half* Qh = qhi + (size_t)b * CDIM * SPAT + h * HD;
    const __half* Ql = qlo + (size_t)b * CDIM * SPAT + h * HD;
    const __half* Kp = kin + (size_t)b * CDIM * SPAT + h * HD;
    const __half* Vp = vt + (size_t)b * SPAT * CDIM + (size_t)(h * HD) * CDIM;
    const int* mrow = mask + (size_t)b * CDIM * CDIM;

    const int wm = (wid & 3) * 32;
    const int wn = (wid >> 2) * 64;
    const int wnd = (wid >> 2) * 32;
    const int lrow = lane & 15, lkc = lane >> 4;

    auto load_k = [&](int buf, int s0) {
        uint32_t kb = sb + FA_K0 + (uint32_t)buf * 16384u;
        #pragma unroll
        for (int p = 0; p < 4; p++) {
            int ci = tid + p * 256;
            int row = ci >> 3, c = ci & 7;
            uint32_t off = (uint32_t)row * 128 + ((uint32_t)(c ^ (row & 7)) << 4);
            cp_async16(kb + off, Kp + (size_t)(s0 + row) * SPAT + c * 8, 16);
        }
    };
    auto load_v = [&](int s0) {
        #pragma unroll
        for (int p = 0; p < 4; p++) {
            int ci = tid + p * 256;
            int row = ci >> 4, cc = ci & 15;
            uint32_t off = (uint32_t)(cc >> 3) * 8192u + (uint32_t)row * 128 +
                           ((uint32_t)((cc & 7) ^ (row & 7)) << 4);
            cp_async16(sb + FA_V + off, Vp + (size_t)row * CDIM + s0 + cc * 8, 16);
        }
    };

    #pragma unroll
    for (int p = 0; p < 4; p++) {
        int ci = tid + p * 256;
        int row = ci >> 3, c = ci & 7;
        uint32_t off = (uint32_t)row * 128 + ((uint32_t)(c ^ (row & 7)) << 4);
        cp_async16(sb + FA_QH + off, Qh + (size_t)(t0 + row) * SPAT + c * 8, 16);
        cp_async16(sb + FA_QL + off, Ql + (size_t)(t0 + row) * SPAT + c * 8, 16);
    }
    load_k(0, 0);
    CP_COMMIT();

    float m_s[4], l_s[4];
    #pragma unroll
    for (int rs = 0; rs < 4; rs++) { m_s[rs] = -3e38f; l_s[rs] = 0.f; }
    float acc_o[2][4][4];
    #pragma unroll
    for (int i = 0; i < 2; i++)
        #pragma unroll
        for (int j = 0; j < 4; j++)
            #pragma unroll
            for (int q = 0; q < 4; q++) acc_o[i][j][q] = 0.f;

    for (int it = 0; it < 8; it++) {
        const int s0 = it * 128;
        CP_WAIT(0);
        __syncthreads();
        load_v(s0); CP_COMMIT();

        float accS[2][8][4];
        #pragma unroll
        for (int i = 0; i < 2; i++)
            #pragma unroll
            for (int j = 0; j < 8; j++)
                #pragma unroll
                for (int q = 0; q < 4; q++) accS[i][j][q] = 0.f;
        {
            const uint32_t sAh = sb + FA_QH, sAl = sb + FA_QL;
            const uint32_t sB = sb + FA_K0 + (uint32_t)(it & 1) * 16384u;
            #pragma unroll
            for (int ks = 0; ks < 4; ks++) {
                const int kc = ks * 2 + lkc;
                uint32_t ah[2][4], al[2][4], bfr[4][4];
                #pragma unroll
                for (int mf = 0; mf < 2; mf++) {
                    int row = wm + mf * 16 + lrow;
                    LDSM_X4(ah[mf], sAh + (uint32_t)row * 128 + ((uint32_t)(kc ^ (row & 7)) << 4));
                }
                #pragma unroll
                for (int np = 0; np < 4; np++) {
                    int row = wn + np * 16 + lrow;
                    LDSM_X4(bfr[np], sB + (uint32_t)row * 128 + ((uint32_t)(kc ^ (row & 7)) << 4));
                }
                #pragma unroll
                for (int mf = 0; mf < 2; mf++)
                    #pragma unroll
                    for (int np = 0; np < 4; np++) {
                        mma16816(accS[mf][np * 2 + 0], ah[mf], bfr[np][0], bfr[np][2]);
                        mma16816(accS[mf][np * 2 + 1], ah[mf], bfr[np][1], bfr[np][3]);
                    }
                #pragma unroll
                for (int mf = 0; mf < 2; mf++) {
                    int row = wm + mf * 16 + lrow;
                    LDSM_X4(al[mf], sAl + (uint32_t)row * 128 + ((uint32_t)(kc ^ (row & 7)) << 4));
                }
                #pragma unroll
                for (int mf = 0; mf < 2; mf++)
                    #pragma unroll
                    for (int np = 0; np < 4; np++) {
                        mma16816(accS[mf][np * 2 + 0], al[mf], bfr[np][0], bfr[np][2]);
                        mma16816(accS[mf][np * 2 + 1], al[mf], bfr[np][1], bfr[np][3]);
                    }
            }
        }

        if (it + 1 < 8) load_k((it + 1) & 1, s0 + 128);
        CP_COMMIT();

        #pragma unroll
        for (int mf = 0; mf < 2; mf++) {
            int t = t0 + wm + mf * 16 + (lane >> 2);
            #pragma unroll
            for (int nf = 0; nf < 8; nf++) {
                int n = s0 + wn + ((nf >> 1) << 4) + ((nf & 1) << 3) + (lane & 3) * 2;
                int2 m0v = *(const int2*)(mrow + (size_t)t * CDIM + n);
                int2 m1v = *(const int2*)(mrow + (size_t)(t + 8) * CDIM + n);
                accS[mf][nf][0] = m0v.x ? accS[mf][nf][0] * 0.125f : -1e9f;
                accS[mf][nf][1] = m0v.y ? accS[mf][nf][1] * 0.125f : -1e9f;
                accS[mf][nf][2] = m1v.x ? accS[mf][nf][2] * 0.125f : -1e9f;
                accS[mf][nf][3] = m1v.y ? accS[mf][nf][3] * 0.125f : -1e9f;
            }
        }

        float lm[4];
        #pragma unroll
        for (int rs = 0; rs < 4; rs++) lm[rs] = -3e38f;
        #pragma unroll
        for (int mf = 0; mf < 2; mf++)
            #pragma unroll
            for (int nf = 0; nf < 8; nf++) {
                lm[mf * 2 + 0] = fmaxf(lm[mf * 2 + 0], fmaxf(accS[mf][nf][0], accS[mf][nf][1]));
                lm[mf * 2 + 1] = fmaxf(lm[mf * 2 + 1], fmaxf(accS[mf][nf][2], accS[mf][nf][3]));
            }
        #pragma unroll
        for (int rs = 0; rs < 4; rs++) {
            lm[rs] = fmaxf(lm[rs], __shfl_xor_sync(0xffffffffu, lm[rs], 1));
            lm[rs] = fmaxf(lm[rs], __shfl_xor_sync(0xffffffffu, lm[rs], 2));
        }
        if ((lane & 3) == 0) {
            #pragma unroll
            for (int rs = 0; rs < 4; rs++) {
                int row = wm + (rs >> 1) * 16 + (lane >> 2) + (rs & 1) * 8;
                rmaxp[(wid >> 2) * 128 + row] = lm[rs];
            }
        }
        __syncthreads();

        float fac[4], mnew[4];
        #pragma unroll
        for (int rs = 0; rs < 4; rs++) {
            int row = wm + (rs >> 1) * 16 + (lane >> 2) + (rs & 1) * 8;
            float cm = fmaxf(rmaxp[row], rmaxp[128 + row]);
            mnew[rs] = fmaxf(m_s[rs], cm);
            fac[rs] = __expf(m_s[rs] - mnew[rs]);
            m_s[rs] = mnew[rs];
        }

        float ls[4];
        #pragma unroll
        for (int rs = 0; rs < 4; rs++) ls[rs] = 0.f;
        #pragma unroll
        for (int mf = 0; mf < 2; mf++) {
            int row0 = wm + mf * 16 + (lane >> 2);
            #pragma unroll
            for (int nf = 0; nf < 8; nf++) {
                int sc = wn + ((nf >> 1) << 4) + ((nf & 1) << 3) + (lane & 3) * 2;
                float p0 = __expf(accS[mf][nf][0] - mnew[mf * 2 + 0]);
                float p1 = __expf(accS[mf][nf][1] - mnew[mf * 2 + 0]);
                float p2 = __expf(accS[mf][nf][2] - mnew[mf * 2 + 1]);
                float p3 = __expf(accS[mf][nf][3] - mnew[mf * 2 + 1]);
                ls[mf * 2 + 0] += p0 + p1;
                ls[mf * 2 + 1] += p2 + p3;
                int sub = sc >> 6, scc = sc & 63;
                uint32_t boff = (uint32_t)sub * 16384u +
                                (((uint32_t)(scc >> 3) ^ ((uint32_t)row0 & 7)) << 4) + (scc & 7) * 2;
                uint32_t boff1 = (uint32_t)sub * 16384u +
                                 (((uint32_t)(scc >> 3) ^ ((uint32_t)(row0 + 8) & 7)) << 4) + (scc & 7) * 2;
                __half h0 = __float2half(p0), h1 = __float2half(p1);
                *(__half2*)(smem + FA_PH + (uint32_t)row0 * 128 + boff) = __halves2half2(h0, h1);
                *(__half2*)(smem + FA_PL + (uint32_t)row0 * 128 + boff) =
                    __halves2half2(__float2half(p0 - __half2float(h0)),
                                   __float2half(p1 - __half2float(h1)));
                __half h2 = __float2half(p2), h3 = __float2half(p3);
                *(__half2*)(smem + FA_PH + (uint32_t)(row0 + 8) * 128 + boff1) = __halves2half2(h2, h3);
                *(__half2*)(smem + FA_PL + (uint32_t)(row0 + 8) * 128 + boff1) =
                    __halves2half2(__float2half(p2 - __half2float(h2)),
                                   __float2half(p3 - __half2float(h3)));
            }
        }
        #pragma unroll
        for (int rs = 0; rs < 4; rs++) {
            ls[rs] += __shfl_xor_sync(0xffffffffu, ls[rs], 1);
            ls[rs] += __shfl_xor_sync(0xffffffffu, ls[rs], 2);
        }
        if ((lane & 3) == 0) {
            #pragma unroll
            for (int rs = 0; rs < 4; rs++) {
                int row = wm + (rs >> 1) * 16 + (lane >> 2) + (rs & 1) * 8;
                rsump[(wid >> 2) * 128 + row] = ls[rs];
            }
        }
        CP_WAIT(1);
        __syncthreads();

        #pragma unroll
        for (int rs = 0; rs < 4; rs++) {
            int row = wm + (rs >> 1) * 16 + (lane >> 2) + (rs & 1) * 8;
            float cs = rsump[row] + rsump[128 + row];
            l_s[rs] = l_s[rs] * fac[rs] + cs;
        }
        #pragma unroll
        for (int mf = 0; mf < 2; mf++)
            #pragma unroll
            for (int nf = 0; nf < 4; nf++) {
                acc_o[mf][nf][0] *= fac[mf * 2 + 0];
                acc_o[mf][nf][1] *= fac[mf * 2 + 0];
                acc_o[mf][nf][2] *= fac[mf * 2 + 1];
                acc_o[mf][nf][3] *= fac[mf * 2 + 1];
            }

        #pragma unroll
        for (int ksi = 0; ksi < 8; ksi++) {
            const int cc = ksi * 2 + lkc;
            const int sub = cc >> 3, c = cc & 7;
            uint32_t ph[2][4], pl[2][4], vf[2][4];
            #pragma unroll
            for (int mf = 0; mf < 2; mf++) {
                int row = wm + mf * 16 + lrow;
                uint32_t off = (uint32_t)sub * 16384u + (uint32_t)row * 128 +
                               ((uint32_t)(c ^ (row & 7)) << 4);
                LDSM_X4(ph[mf], sb + FA_PH + off);
                LDSM_X4(pl[mf], sb + FA_PL + off);
            }
            #pragma unroll
            for (int np = 0; np < 2; np++) {
                int row = wnd + np * 16 + lrow;
                uint32_t off = (uint32_t)sub * 8192u + (uint32_t)row * 128 +
                               ((uint32_t)(c ^ (row & 7)) << 4);
                LDSM_X4(vf[np], sb + FA_V + off);
            }
            #pragma unroll
            for (int mf = 0; mf < 2; mf++)
                #pragma unroll
                for (int np = 0; np < 2; np++) {
                    mma16816(acc_o[mf][np * 2 + 0], ph[mf], vf[np][0], vf[np][2]);
                    mma16816(acc_o[mf][np * 2 + 1], ph[mf], vf[np][1], vf[np][3]);
                    mma16816(acc_o[mf][np * 2 + 0], pl[mf], vf[np][0], vf[np][2]);
                    mma16816(acc_o[mf][np * 2 + 1], pl[mf], vf[np][1], vf[np][3]);
                }
        }
    }

    float invl[4];
    #pragma unroll
    for (int rs = 0; rs < 4; rs++) invl[rs] = 1.0f / l_s[rs];
    #pragma unroll
    for (int mf = 0; mf < 2; mf++) {
        int t = t0 + wm + mf * 16 + (lane >> 2);
        #pragma unroll
        for (int nf = 0; nf < 4; nf++) {
            int n = h * HD + wnd + ((nf >> 1) << 4) + ((nf & 1) << 3) + (lane & 3) * 2;
            hsplit_store2(aoh, aol, ((size_t)b * CDIM + t) * SPAT + n,
                          acc_o[mf][nf][0] * invl[mf * 2 + 0],
                          acc_o[mf][nf][1] * invl[mf * 2 + 0]);
            hsplit_store2(aoh, aol, ((size_t)b * CDIM + t + 8) * SPAT + n,
                          acc_o[mf][nf][2] * invl[mf * 2 + 1],
                          acc_o[mf][nf][3] * invl[mf * 2 + 1]);
        }
    }
}

// ---------------- output projection, fp16 2-term, BK=64 --------------------
// Stage (48KB): Ah @0 | Al @16384 | B @32768
#define PJ_STAGE 49152
__global__ __launch_bounds__(256)
void proj_mma(const __half* __restrict__ aoh, const __half* __restrict__ aol,
              const __half* __restrict__ wo,
              const float* __restrict__ bo, float* __restrict__ out) {
    extern __shared__ char smem[];
    const uint32_t sb = smem_u32(smem);
    const int tid = threadIdx.x, wid = tid >> 5, lane = tid & 31;
    const int row0 = blockIdx.y * 128, m0 = blockIdx.x * 128;

    const __half* Ah = aoh + (size_t)row0 * CDIM;
    const __half* Al = aol + (size_t)row0 * CDIM;
    const __half* Bp = wo + (size_t)m0 * CDIM;

    const int wm = (wid & 3) * 32, wn = (wid >> 2) * 64;
    const int lrow = lane & 15, lkc = lane >> 4;
    const int arow = tid >> 3, ac = tid & 7;

    float acc[2][8][4];
    #pragma unroll
    for (int i = 0; i < 2; i++)
        #pragma unroll
        for (int j = 0; j < 8; j++)
            #pragma unroll
            for (int q = 0; q < 4; q++) acc[i][j][q] = 0.f;

    auto load_stage = [&](uint32_t base, int it) {
        #pragma unroll
        for (int p = 0; p < 4; p++) {
            int row = arow + p * 32;
            uint32_t off = (uint32_t)row * 128 + ((uint32_t)(ac ^ (row & 7)) << 4);
            cp_async16(base + off, Ah + (size_t)row * CDIM + it * 64 + ac * 8, 16);
            cp_async16(base + 16384u + off, Al + (size_t)row * CDIM + it * 64 + ac * 8, 16);
            cp_async16(base + 32768u + off, Bp + (size_t)row * CDIM + it * 64 + ac * 8, 16);
        }
        CP_COMMIT();
    };

    auto compute_stage = [&](uint32_t sA) {
        const uint32_t sAl = sA + 16384u, sB = sA + 32768u;
        #pragma unroll
        for (int ks = 0; ks < 4; ks++) {
            const int kc = ks * 2 + lkc;
            uint32_t ah[2][4], al[2][4], bfr[4][4];
            #pragma unroll
            for (int mf = 0; mf < 2; mf++) {
                int row = wm + mf * 16 + lrow;
                LDSM_X4(ah[mf], sA + (uint32_t)row * 128 + ((uint32_t)(kc ^ (row & 7)) << 4));
            }
            #pragma unroll
            for (int np = 0; np < 4; np++) {
                int row = wn + np * 16 + lrow;
                LDSM_X4(bfr[np], sB + (uint32_t)row * 128 + ((uint32_t)(kc ^ (row & 7)) << 4));
            }
            #pragma unroll
            for (int mf = 0; mf < 2; mf++)
                #pragma unroll
                for (int np = 0; np < 4; np++) {
                    mma16816(acc[mf][np * 2 + 0], ah[mf], bfr[np][0], bfr[np][2]);
                    mma16816(acc[mf][np * 2 + 1], ah[mf], bfr[np][1], bfr[np][3]);
                }
            #pragma unroll
            for (int mf = 0; mf < 2; mf++) {
                int row = wm + mf * 16 + lrow;
                LDSM_X4(al[mf], sAl + (uint32_t)row * 128 + ((uint32_t)(kc ^ (row & 7)) << 4));
            }
            #pragma unroll
            for (int mf = 0; mf < 2; mf++)
                #pragma unroll
                for (int np = 0; np < 4; np++) {
                    mma16816(acc[mf][np * 2 + 0], al[mf], bfr[np][0], bfr[np][2]);
                    mma16816(acc[mf][np * 2 + 1], al[mf], bfr[np][1], bfr[np][3]);
                }
        }
    };

    load_stage(sb, 0);
    for (int it = 0; it < 16; it += 2) {
        CP_WAIT(0);
        __syncthreads();
        if (it + 1 < 16) load_stage(sb + PJ_STAGE, it + 1);
        compute_stage(sb);
        CP_WAIT(0);
        __syncthreads();
        if (it + 2 < 16) load_stage(sb, it + 2);
        compute_stage(sb + PJ_STAGE);
    }

    #pragma unroll
    for (int mf = 0; mf < 2; mf++) {
        int r = row0 + wm + mf * 16 + (lane >> 2);
        #pragma unroll
        for (int nf = 0; nf < 8; nf++) {
            int n = m0 + wn + ((nf >> 1) << 4) + ((nf & 1) << 3) + (lane & 3) * 2;
            float b0 = bo[n], b1 = bo[n + 1];
            float2 v0 = {acc[mf][nf][0] + b0, acc[mf][nf][1] + b1};
            float2 v1 = {acc[mf][nf][2] + b0, acc[mf][nf][3] + b1};
            *(float2*)(out + (size_t)r * CDIM + n) = v0;
            *(float2*)(out + (size_t)(r + 8) * CDIM + n) = v1;
        }
    }
}

// ---------------- launch ---------------------------------------------------
extern "C" void kernel_launch(void* const* d_in, const int* in_sizes, int n_in,
                              void* d_out, int out_size) {
    const float* q  = (const float*)d_in[0];
    const float* k  = (const float*)d_in[1];
    const float* v  = (const float*)d_in[2];
    const float* Wq = (const float*)d_in[3];
    const float* bq = (const float*)d_in[4];
    const float* Wk = (const float*)d_in[5];
    const float* bk = (const float*)d_in[6];
    const float* Wv = (const float*)d_in[7];
    const float* bv = (const float*)d_in[8];
    const float* Wo = (const float*)d_in[9];
    const float* bo = (const float*)d_in[10];
    const int*   mask = (const int*)d_in[11];
    float* out = (float*)d_out;

    __half *whi, *wlo, *gin, *qhi, *qlo, *kh, *vh, *vt, *wo, *aoh, *aol;
    cudaGetSymbolAddress((void**)&whi, g_whi);
    cudaGetSymbolAddress((void**)&wlo, g_wlo);
    cudaGetSymbolAddress((void**)&gin, g_in);
    cudaGetSymbolAddress((void**)&qhi, g_qhi);
    cudaGetSymbolAddress((void**)&qlo, g_qlo);
    cudaGetSymbolAddress((void**)&kh,  g_k);
    cudaGetSymbolAddress((void**)&vh,  g_v);
    cudaGetSymbolAddress((void**)&vt,  g_vt);
    cudaGetSymbolAddress((void**)&wo,  g_wo);
    cudaGetSymbolAddress((void**)&aoh, g_aohi);
    cudaGetSymbolAddress((void**)&aol, g_aolo);

    cudaFuncSetAttribute(conv_mma,   cudaFuncAttributeMaxDynamicSharedMemorySize, 2 * CV_STAGE);
    cudaFuncSetAttribute(flash_attn, cudaFuncAttributeMaxDynamicSharedMemorySize, FA_SMEM);
    cudaFuncSetAttribute(proj_mma,   cudaFuncAttributeMaxDynamicSharedMemorySize, 2 * PJ_STAGE);

    split_w<<<dim3(CDIM, 3), 256>>>(Wq, Wk, Wv, whi, wlo);
    wo_half<<<4096, 256>>>(Wo, wo);
    transpose_in<<<dim3(32, 32, 24), dim3(32, 8)>>>(q, k, v, gin);

    conv_mma<<<dim3(8, 8, 24), 256, 2 * CV_STAGE>>>(whi, wlo, gin, bq, bk, bv,
                                                    qhi, qlo, kh, vh);

    tr_half<<<dim3(32, 32, 8), dim3(32, 8)>>>(vh, vt);

    flash_attn<<<dim3(8, BATCH * NH), 256, FA_SMEM>>>(qhi, qlo, kh, vt, mask, aoh, aol);

    proj_mma<<<dim3(8, 64), 256, 2 * PJ_STAGE>>>(aoh, aol, wo, bo, out);
}